// round 6
// baseline (speedup 1.0000x reference)
#include <cuda_runtime.h>
#include <math.h>

#define BB 2
#define CC 128
#define NXY 4096
#define NN 8192            // nodes per batch (x then y)
#define KTOT 12
#define MROWS (BB*NN)      // 16384
#define NT 64              // tiles per modality side (4096/64)

typedef unsigned long long u64;

// packed fp32x2 helpers (Blackwell f32x2 pipe; only reachable via PTX)
__device__ __forceinline__ void fma2(u64& acc, u64 a, u64 b) {
    asm("fma.rn.f32x2 %0, %1, %2, %0;" : "+l"(acc) : "l"(a), "l"(b));
}
__device__ __forceinline__ u64 pk2(float x) {
    u64 r; asm("mov.b64 %0, {%1, %1};" : "=l"(r) : "f"(x)); return r;
}
__device__ __forceinline__ u64 pk2p(float x, float y) {
    u64 r; asm("mov.b64 %0, {%1, %2};" : "=l"(r) : "f"(x), "f"(y)); return r;
}
__device__ __forceinline__ float2 upk(u64 p) {
    float2 r; asm("mov.b64 {%0, %1}, %2;" : "=f"(r.x), "=f"(r.y) : "l"(p)); return r;
}
// order-preserving fp32 -> u32 (ascending float => ascending uint)
__device__ __forceinline__ unsigned okey(float s) {
    unsigned u = __float_as_uint(s);
    return (u & 0x80000000u) ? ~u : (u | 0x80000000u);
}

// ---------------- scratch (device globals; no allocation allowed) -------------
__device__ float g_feat[MROWS*CC];   // 8 MB  [b][node][c]
__device__ float g_rel [MROWS*CC];   // 8 MB
__device__ float g_out [MROWS*CC];   // 8 MB
__device__ float g_norm[MROWS];
__device__ int   g_nbr [MROWS*KTOT];
__device__ float g_sum[CC];
__device__ float g_sumsq[CC];
// partial top-K staging: key = (okey(score)<<32) | cand_idx_within_modality
__device__ u64 g_ps[BB*2*NT*9*NXY];  // 75 MB  [b][mod][T][u][q]  (inner KNN)
__device__ u64 g_pc[BB*2*NT*3*NXY];  // 25 MB  [b][mod][T][u][q]  (cross KNN)

#define PS(b,mod,T,u,q) ((((size_t)(((b)*2+(mod))*NT+(T))*9 + (u))*NXY) + (q))
#define PC(b,mod,T,u,q) ((((size_t)(((b)*2+(mod))*NT+(T))*3 + (u))*NXY) + (q))

// ---------------- 1) transpose inputs [B,C,N] -> feat [B,N,C] ----------------
__global__ void build_feat(const float* __restrict__ x, const float* __restrict__ y) {
    const int b = blockIdx.z, part = blockIdx.y;
    const int n0 = blockIdx.x * 32;
    const float* src = part ? y : x;            // [B][C][NXY]
    __shared__ float s[CC * 33];
    const int t = threadIdx.x;
#pragma unroll
    for (int p = 0; p < 16; ++p) {
        int c  = p * 8 + (t >> 5);
        int nn = t & 31;
        s[c * 33 + nn] = src[(size_t)(b * CC + c) * NXY + n0 + nn];
    }
    __syncthreads();
    const int nodeb = part * NXY + n0;
#pragma unroll
    for (int p = 0; p < 16; ++p) {
        int nn = p * 2 + (t >> 7);
        int c  = t & 127;
        g_feat[(size_t)(b * NN + nodeb + nn) * CC + c] = s[c * 33 + nn];
    }
}

// ---------------- 2) per-node squared norms ----------------------------------
__global__ void calc_norm() {
    const int node = blockIdx.x * 8 + (threadIdx.x >> 5);
    const int lane = threadIdx.x & 31;
    const float* f = g_feat + (size_t)node * CC;
    float s = 0.f;
#pragma unroll
    for (int i = 0; i < 4; ++i) { float v = f[lane + 32 * i]; s += v * v; }
#pragma unroll
    for (int o = 16; o; o >>= 1) s += __shfl_down_sync(0xffffffffu, s, o);
    if (!lane) g_norm[node] = s;
}

// ---------------- 3) tiled distance-dot + dual-orientation top-K -------------
// Each 64x64 tile of dot products computed ONCE, scanned as rows (queries=I)
// and as cols (queries=J). Sym kinds (0:x-x, 1:y-y) use upper triangle I<=J;
// cross kind (2: x rows vs y cols) covers the full rectangle and serves both
// x->y (rows) and y->x (cols). Partial top-K lists -> g_ps/g_pc.
__global__ void __launch_bounds__(256) knn_tile() {
    const int z = blockIdx.z;
    const int b = z / 3, kind = z % 3;
    const int I = blockIdx.y, J = blockIdx.x;
    if (kind < 2 && I > J) return;
    const int mod_q = (kind == 1) ? 1 : 0;
    const int mod_c = (kind == 0) ? 0 : 1;
    const int qoff = mod_q * NXY + I * 64;      // node base within batch
    const int coff = mod_c * NXY + J * 64;
    const int t = threadIdx.x;
    const int tx = t & 15, ty = t >> 4;

    __shared__ float sQ[32 * 68];      // [k][query]
    __shared__ float sC[32 * 68];      // [k][cand]
    __shared__ float sD[64 * 68];      // dot staging
    __shared__ float sNq[64], sNc[64];
    __shared__ u64   sMK[64 * 2 * 9];

    const float* fb = g_feat + (size_t)b * NN * CC;
    const float* nr = g_norm + b * NN;
    if (t < 64) sNq[t] = nr[qoff + t];
    else if (t < 128) sNc[t - 64] = nr[coff + t - 64];

    u64 acc2[4][2];
#pragma unroll
    for (int i = 0; i < 4; ++i) { acc2[i][0] = 0ull; acc2[i][1] = 0ull; }

    for (int kc = 0; kc < CC; kc += 32) {
        __syncthreads();
#pragma unroll
        for (int u = 0; u < 2; ++u) {
            int e = t + 256 * u;
            int q = e >> 3, kg = e & 7;
            float4 a4 = *(const float4*)&fb[(size_t)(qoff + q) * CC + kc + kg * 4];
            sQ[(kg * 4 + 0) * 68 + q] = a4.x;
            sQ[(kg * 4 + 1) * 68 + q] = a4.y;
            sQ[(kg * 4 + 2) * 68 + q] = a4.z;
            sQ[(kg * 4 + 3) * 68 + q] = a4.w;
            float4 c4 = *(const float4*)&fb[(size_t)(coff + q) * CC + kc + kg * 4];
            sC[(kg * 4 + 0) * 68 + q] = c4.x;
            sC[(kg * 4 + 1) * 68 + q] = c4.y;
            sC[(kg * 4 + 2) * 68 + q] = c4.z;
            sC[(kg * 4 + 3) * 68 + q] = c4.w;
        }
        __syncthreads();
#pragma unroll
        for (int k = 0; k < 32; ++k) {
            float4 a4 = *(const float4*)(sQ + k * 68 + ty * 4);
            float4 c4 = *(const float4*)(sC + k * 68 + tx * 4);
            u64 c0 = pk2p(c4.x, c4.y), c1 = pk2p(c4.z, c4.w);
            u64 aa0 = pk2(a4.x), aa1 = pk2(a4.y), aa2 = pk2(a4.z), aa3 = pk2(a4.w);
            fma2(acc2[0][0], aa0, c0); fma2(acc2[0][1], aa0, c1);
            fma2(acc2[1][0], aa1, c0); fma2(acc2[1][1], aa1, c1);
            fma2(acc2[2][0], aa2, c0); fma2(acc2[2][1], aa2, c1);
            fma2(acc2[3][0], aa3, c0); fma2(acc2[3][1], aa3, c1);
        }
    }
    __syncthreads();
#pragma unroll
    for (int i = 0; i < 4; ++i) {
        float2 p0 = upk(acc2[i][0]);
        float2 p1 = upk(acc2[i][1]);
        float4 d; d.x = p0.x; d.y = p0.y; d.z = p1.x; d.w = p1.y;
        *(float4*)(sD + (ty * 4 + i) * 68 + tx * 4) = d;
    }
    __syncthreads();

    const int KW = (kind == 2) ? 3 : 9;

    // ---- row scan: queries = I tile, cands = J tile ----
    {
        u64 ld[9];
        if (t < 128) {
            const int q = t & 63, ch = t >> 6;
#pragma unroll
            for (int u = 0; u < 9; ++u) ld[u] = 0xFFFFFFFFFFFFFFFFull;
            const float* row = sD + q * 68 + ch * 32;
#pragma unroll
            for (int m = 0; m < 32; ++m) {
                float s = sNc[ch * 32 + m] - 2.f * row[m];
                u64 key = ((u64)okey(s) << 32) | (unsigned)(J * 64 + ch * 32 + m);
                if (key < ld[8]) {
                    int p = 8;
#pragma unroll
                    for (int u = 7; u >= 0; --u)
                        if (key < ld[u]) { ld[u + 1] = ld[u]; p = u; }
                    ld[p] = key;
                }
            }
#pragma unroll
            for (int u = 0; u < 9; ++u) sMK[(q * 2 + ch) * 9 + u] = ld[u];
        }
        __syncthreads();
        if (t < 64) {
            u64 prev = 0;
            const u64* l0 = sMK + (t * 2) * 9;
            for (int m = 0; m < KW; ++m) {
                u64 best = 0xFFFFFFFFFFFFFFFFull;
#pragma unroll
                for (int u = 0; u < 18; ++u) {
                    u64 v = l0[u];
                    if (v > prev && v < best) best = v;
                }
                prev = best;
                size_t off = (kind == 2) ? PC(b, 0, J, m, I * 64 + t)
                                         : PS(b, mod_q, J, m, I * 64 + t);
                ((kind == 2) ? g_pc : g_ps)[off] = best;
            }
        }
    }

    // ---- col scan: queries = J tile, cands = I tile (skip sym diagonal) ----
    if (kind == 2 || I < J) {
        __syncthreads();
        u64 ld[9];
        if (t < 128) {
            const int c = t & 63, ch = t >> 6;
#pragma unroll
            for (int u = 0; u < 9; ++u) ld[u] = 0xFFFFFFFFFFFFFFFFull;
#pragma unroll
            for (int m = 0; m < 32; ++m) {
                int rr = ch * 32 + m;
                float s = sNq[rr] - 2.f * sD[rr * 68 + c];
                u64 key = ((u64)okey(s) << 32) | (unsigned)(I * 64 + rr);
                if (key < ld[8]) {
                    int p = 8;
#pragma unroll
                    for (int u = 7; u >= 0; --u)
                        if (key < ld[u]) { ld[u + 1] = ld[u]; p = u; }
                    ld[p] = key;
                }
            }
#pragma unroll
            for (int u = 0; u < 9; ++u) sMK[(c * 2 + ch) * 9 + u] = ld[u];
        }
        __syncthreads();
        if (t < 64) {
            u64 prev = 0;
            const u64* l0 = sMK + (t * 2) * 9;
            for (int m = 0; m < KW; ++m) {
                u64 best = 0xFFFFFFFFFFFFFFFFull;
#pragma unroll
                for (int u = 0; u < 18; ++u) {
                    u64 v = l0[u];
                    if (v > prev && v < best) best = v;
                }
                prev = best;
                size_t off = (kind == 2) ? PC(b, 1, I, m, J * 64 + t)
                                         : PS(b, mod_q, I, m, J * 64 + t);
                ((kind == 2) ? g_pc : g_ps)[off] = best;
            }
        }
    }
}

// ---------------- 3b) merge partial lists -> g_nbr ---------------------------
__global__ void knn_merge() {
    const int tid = blockIdx.x * 256 + threadIdx.x;   // 16384 = B*2*NXY
    const int b = tid >> 13, mod = (tid >> 12) & 1, q = tid & (NXY - 1);
    int* dst = g_nbr + (size_t)(b * NN + mod * NXY + q) * KTOT;

    {   // inner: top-9 over 64 tiles x 9
        u64 ld[9];
#pragma unroll
        for (int u = 0; u < 9; ++u) ld[u] = 0xFFFFFFFFFFFFFFFFull;
        const u64* src = g_ps + PS(b, mod, 0, 0, q);
        for (int e = 0; e < NT * 9; ++e) {
            u64 key = src[(size_t)e * NXY];
            if (key < ld[8]) {
                int p = 8;
#pragma unroll
                for (int u = 7; u >= 0; --u)
                    if (key < ld[u]) { ld[u + 1] = ld[u]; p = u; }
                ld[p] = key;
            }
        }
        const int base = mod * NXY;
#pragma unroll
        for (int m = 0; m < 9; ++m) dst[m] = base + (int)(unsigned)(ld[m] & 0xFFFFFFFFull);
    }
    {   // cross: top-3 over 64 tiles x 3
        u64 ld[3];
#pragma unroll
        for (int u = 0; u < 3; ++u) ld[u] = 0xFFFFFFFFFFFFFFFFull;
        const u64* src = g_pc + PC(b, mod, 0, 0, q);
        for (int e = 0; e < NT * 3; ++e) {
            u64 key = src[(size_t)e * NXY];
            if (key < ld[2]) {
                int p = 2;
#pragma unroll
                for (int u = 1; u >= 0; --u)
                    if (key < ld[u]) { ld[u + 1] = ld[u]; p = u; }
                ld[p] = key;
            }
        }
        const int base = (1 - mod) * NXY;
#pragma unroll
        for (int m = 0; m < 3; ++m) dst[9 + m] = base + (int)(unsigned)(ld[m] & 0xFFFFFFFFull);
    }
}

// ---------------- 4) max-relative gather -------------------------------------
__global__ void rel_kernel() {
    const int r = blockIdx.x;           // 0..MROWS-1
    const int b = r >> 13;              // NN = 8192
    const int c = threadIdx.x;
    const int* nb = g_nbr + (size_t)r * KTOT;
    const float* fb = g_feat + (size_t)b * NN * CC;
    float m = -3.4e38f;
#pragma unroll
    for (int k = 0; k < KTOT; ++k) {
        int j = nb[k];
        m = fmaxf(m, fb[(size_t)j * CC + c]);
    }
    g_rel[(size_t)r * CC + c] = m - g_feat[(size_t)r * CC + c];
}

// ---------------- 5) 1x1 conv: out = [feat|rel] @ W[l]^T + b -----------------
__global__ void __launch_bounds__(256) conv_kernel(const float* __restrict__ W,
                                                   const float* __restrict__ bias, int l) {
    const int r0 = blockIdx.x * 64;
    const int t = threadIdx.x;
    const int ty = t >> 5, tx = t & 31;
    __shared__ float sH[64 * 33];
    __shared__ float sW[32 * 132];   // [k][channel]
    const float* Wl = W + (size_t)l * CC * 2 * CC;
    u64 acc2[8][2];
#pragma unroll
    for (int i = 0; i < 8; ++i) { acc2[i][0] = 0ull; acc2[i][1] = 0ull; }

    for (int kc = 0; kc < 2 * CC; kc += 32) {
        __syncthreads();
        const float* src = kc < CC ? g_feat : g_rel;
        const int ko = kc < CC ? kc : kc - CC;
#pragma unroll
        for (int u = 0; u < 8; ++u) {
            int e = t + 256 * u; int row = e >> 5, k = e & 31;
            sH[row * 33 + k] = src[(size_t)(r0 + row) * CC + ko + k];
        }
#pragma unroll
        for (int u = 0; u < 4; ++u) {          // 128c x 8 k-groups of 4
            int e = t + 256 * u;
            int c = e >> 3, kg = e & 7;
            float4 w4 = *(const float4*)&Wl[(size_t)c * 2 * CC + kc + kg * 4];
            sW[(kg * 4 + 0) * 132 + c] = w4.x;
            sW[(kg * 4 + 1) * 132 + c] = w4.y;
            sW[(kg * 4 + 2) * 132 + c] = w4.z;
            sW[(kg * 4 + 3) * 132 + c] = w4.w;
        }
        __syncthreads();
#pragma unroll
        for (int k = 0; k < 32; ++k) {
            float4 w4 = *(const float4*)(sW + k * 132 + tx * 4);
            u64 w0 = pk2p(w4.x, w4.y);
            u64 w1 = pk2p(w4.z, w4.w);
#pragma unroll
            for (int i = 0; i < 8; ++i) {
                u64 ap = pk2(sH[(ty + 8 * i) * 33 + k]);
                fma2(acc2[i][0], ap, w0);
                fma2(acc2[i][1], ap, w1);
            }
        }
    }
    float4 bv = *(const float4*)&bias[l * CC + tx * 4];
#pragma unroll
    for (int i = 0; i < 8; ++i) {
        float2 p0 = upk(acc2[i][0]);
        float2 p1 = upk(acc2[i][1]);
        float4 o; o.x = p0.x + bv.x; o.y = p0.y + bv.y; o.z = p1.x + bv.z; o.w = p1.y + bv.w;
        *(float4*)&g_out[(size_t)(r0 + ty + 8 * i) * CC + tx * 4] = o;
    }
}

// ---------------- 6) batchnorm stats -----------------------------------------
__global__ void zero_stats() {
    int t = threadIdx.x;
    if (t < CC) { g_sum[t] = 0.f; g_sumsq[t] = 0.f; }
}

__global__ void stats_kernel() {
    const int r0 = blockIdx.x * 128;
    const int t = threadIdx.x;
    const int c = t & 127, half = t >> 7;
    float s = 0.f, ss = 0.f;
#pragma unroll 4
    for (int i = 0; i < 64; ++i) {
        float v = g_out[(size_t)(r0 + half + 2 * i) * CC + c];
        s += v; ss += v * v;
    }
    __shared__ float aS[256], aSS[256];
    aS[t] = s; aSS[t] = ss;
    __syncthreads();
    if (t < 128) {
        atomicAdd(&g_sum[c],   aS[t] + aS[t + 128]);
        atomicAdd(&g_sumsq[c], aSS[t] + aSS[t + 128]);
    }
}

// ---------------- 7) BN + tanh-GELU + residual (in place on feat) ------------
__global__ void bn_apply(const float* __restrict__ gamma, const float* __restrict__ beta, int l) {
    const int i = blockIdx.x * 256 + threadIdx.x;   // MROWS*CC elems exactly
    const int c = i & 127;
    const float inv_n = 1.f / (float)MROWS;
    float mean = g_sum[c] * inv_n;
    float var  = g_sumsq[c] * inv_n - mean * mean;
    float sc = rsqrtf(var + 1e-5f) * gamma[l * CC + c];
    float v = (g_out[i] - mean) * sc + beta[l * CC + c];
    float g = 0.5f * v * (1.f + tanhf(0.7978845608f * (v + 0.044715f * v * v * v)));
    g_feat[i] += g;
}

// ---------------- 8) transpose feat -> output [B,C,NX,1] ++ [B,C,NY,1] -------
__global__ void write_out(float* __restrict__ out) {
    const int b = blockIdx.z, part = blockIdx.y;
    const int n0 = blockIdx.x * 32;
    const int t = threadIdx.x;
    __shared__ float s[32 * 129];
#pragma unroll
    for (int p = 0; p < 16; ++p) {
        int nn = p * 2 + (t >> 7), c = t & 127;
        s[nn * 129 + c] = g_feat[(size_t)(b * NN + part * NXY + n0 + nn) * CC + c];
    }
    __syncthreads();
    float* dst = out + (size_t)part * BB * CC * NXY;
#pragma unroll
    for (int p = 0; p < 16; ++p) {
        int c = p * 8 + (t >> 5), nn = t & 31;
        dst[(size_t)(b * CC + c) * NXY + n0 + nn] = s[nn * 129 + c];
    }
}

// ---------------- launch ------------------------------------------------------
extern "C" void kernel_launch(void* const* d_in, const int* in_sizes, int n_in,
                              void* d_out, int out_size) {
    const float* x     = (const float*)d_in[0];
    const float* y     = (const float*)d_in[1];
    const float* W     = (const float*)d_in[2];
    const float* bias  = (const float*)d_in[3];
    const float* gamma = (const float*)d_in[4];
    const float* beta  = (const float*)d_in[5];

    build_feat<<<dim3(NXY / 32, 2, BB), 256>>>(x, y);
    calc_norm<<<MROWS / 8, 256>>>();
    knn_tile<<<dim3(NT, NT, 3 * BB), 256>>>();
    knn_merge<<<64, 256>>>();

    for (int l = 0; l < 2; ++l) {
        rel_kernel<<<MROWS, 128>>>();
        conv_kernel<<<MROWS / 64, 256>>>(W, bias, l);
        zero_stats<<<1, 128>>>();
        stats_kernel<<<128, 256>>>();
        bn_apply<<<MROWS * CC / 256, 256>>>(gamma, beta, l);
    }

    write_out<<<dim3(NXY / 32, 2, BB), 256>>>((float*)d_out);
}